// round 13
// baseline (speedup 1.0000x reference)
#include <cuda_runtime.h>

// Kalman filter, simple-form update, 2x4-block-per-lane layout with
// TWO independent batch chains interleaved per lane (software SMT).
// B=4096, T=200, S=8, M=2.
// 8 lanes per batch: lane (rp, c) owns P[2rp..2rp+1][4c..4c+3].
// 4 lane-groups x 2 interleaved chains = 8 batches per 32-lane warp,
// 512 warps. Phases of the two chains are interleaved between the shared
// __syncwarp()s so each chain's LDS/shfl latency is hidden by the other's
// FFMAs inside the same warp.
// WSF = 180: per-instruction active workspace stride 2*WSF = 360 == 8 mod 32
// -> the 4 lane-groups land on bank offsets {0,8,16,24}; all broadcast matmul
// LDS verified bank-disjoint.

namespace {
constexpr int Bb  = 4096;
constexpr int Tt  = 200;
constexpr int WSF = 180;
constexpr unsigned FULL = 0xffffffffu;
// per-batch SMEM float offsets (16B-aligned)
constexpr int OPUL = 0;    // Pu cols 0..3, row j at +j*4
constexpr int OPUH = 36;   // Pu cols 4..7
constexpr int OFA  = 68;   // F rows 0..3, 8 f/row, [lo|hi]
constexpr int OFB  = 104;  // F rows 4..7, 8 f/row, [hi|lo]
constexpr int OHPL = 136;  // (hp0,hp1) interleaved, cols 0..3
constexpr int OHPH = 148;  // cols 4..7
constexpr int OMU  = 156;  // updated mean (8)
constexpr int OMN  = 164;  // predicted mean (8)
}

__global__ __launch_bounds__(32)
void kalman_kernel(const float* __restrict__ gy,      // [B,T,2]
                   const float* __restrict__ gF,      // [B,T,8,8]
                   const float* __restrict__ gH,      // [B,T,2,8]
                   const float* __restrict__ gQ,      // [8,8]
                   const float* __restrict__ gR,      // [2,2]
                   const float* __restrict__ gMean0,  // [B,8]
                   const float* __restrict__ gCov0,   // [8,8]
                   float* __restrict__ oMean,         // [B,T,8]
                   float* __restrict__ oCov)          // [B,T,8,8]
{
    __shared__ __align__(16) float sw[8 * WSF];
    const int lane = threadIdx.x;
    const int lb   = lane >> 3;          // lane-group (0..3)
    const int c    = (lane >> 2) & 1;    // column half
    const int rp   = lane & 3;           // row pair
    const int ra   = 2 * rp;             // owned rows ra, ra+1
    const int cb   = 4 * c;              // own column base
    const int ob   = 4 - cb;             // other column base

    const int opu  = c ? OPUH : OPUL;
    const int ohp  = c ? OHPH : OHPL;
    const int ofk  = c ? OFB  : OFA;
    const int fblk = (rp < 2) ? OFA : OFB;
    const int fcof = (rp < 2) ? cb : ob;
    const int frow = (rp & 1) * 16;
    const int ohpw = ((rp < 2) ? OHPL : OHPH) + 4 * (rp & 1);

    const float R00 = gR[0], R01 = gR[1], R10 = gR[2], R11 = gR[3];
    float Qa[4], Qb[4];
#pragma unroll
    for (int m = 0; m < 4; ++m) {
        Qa[m] = gQ[ra * 8 + cb + m];
        Qb[m] = gQ[(ra + 1) * 8 + cb + m];
    }

    // ---- per-chain state ----
    float* wsp[2];
    const float *Fb[2], *Hb[2], *yb[2];
    float *omb[2], *ocb[2];
    float pra[2][4], prb[2][4];
    float4 fA4[2], fB4[2], hA[2], hC[2];
    float2 yv[2];

#pragma unroll
    for (int u = 0; u < 2; ++u) {
        const int b = blockIdx.x * 8 + lb * 2 + u;
        wsp[u] = sw + (lb * 2 + u) * WSF;
        Fb[u]  = gF + (size_t)b * Tt * 64;
        Hb[u]  = gH + (size_t)b * Tt * 16;
        yb[u]  = gy + (size_t)b * Tt * 2;
        omb[u] = oMean + (size_t)b * Tt * 8;
        ocb[u] = oCov  + (size_t)b * Tt * 64;

        // init: own 2x4 block of P; t=0 outputs
        const float4 p0 = *(const float4*)(gCov0 + ra * 8 + cb);
        const float4 p1 = *(const float4*)(gCov0 + (ra + 1) * 8 + cb);
        pra[u][0]=p0.x; pra[u][1]=p0.y; pra[u][2]=p0.z; pra[u][3]=p0.w;
        prb[u][0]=p1.x; prb[u][1]=p1.y; prb[u][2]=p1.z; prb[u][3]=p1.w;
        *(float4*)(ocb[u] + ra * 8 + cb)       = p0;
        *(float4*)(ocb[u] + (ra + 1) * 8 + cb) = p1;
        if (c == 0) {
            const float2 m0 = *(const float2*)(gMean0 + b * 8 + ra);
            *(float2*)(wsp[u] + OMN + ra) = m0;
            *(float2*)(omb[u] + ra)       = m0;
        }

        // prefetch step 0
        fA4[u] = *(const float4*)(Fb[u] + ra * 8 + cb);
        fB4[u] = *(const float4*)(Fb[u] + (ra + 1) * 8 + cb);
        hA[u]  = *(const float4*)(Hb[u] + cb);
        hC[u]  = *(const float4*)(Hb[u] + 8 + cb);
        yv[u]  = *(const float2*)(yb[u]);
    }
    __syncwarp();

    for (int t = 0; t < Tt - 1; ++t) {
        float fa[2][4], fr2[2][4], hao[2][4], hco[2][4];
        float y0[2], y1[2];
        float hp0a[2], hp1a[2], hp0b[2], hp1b[2];
        float r0[2], r1[2];
        float foa[2][4], fob[2][4];

        // ---- copy operands + prefetch next + phase 1, interleaved ----
#pragma unroll
        for (int u = 0; u < 2; ++u) {
            fa[u][0]=fA4[u].x; fa[u][1]=fA4[u].y; fa[u][2]=fA4[u].z; fa[u][3]=fA4[u].w;
            fr2[u][0]=fB4[u].x; fr2[u][1]=fB4[u].y; fr2[u][2]=fB4[u].z; fr2[u][3]=fB4[u].w;
            hao[u][0]=hA[u].x; hao[u][1]=hA[u].y; hao[u][2]=hA[u].z; hao[u][3]=hA[u].w;
            hco[u][0]=hC[u].x; hco[u][1]=hC[u].y; hco[u][2]=hC[u].z; hco[u][3]=hC[u].w;
            y0[u]=yv[u].x; y1[u]=yv[u].y;

            const float* Fn = Fb[u] + (size_t)(t + 1) * 64;
            fA4[u] = *(const float4*)(Fn + ra * 8 + cb);
            fB4[u] = *(const float4*)(Fn + (ra + 1) * 8 + cb);
            const float* Hn = Hb[u] + (size_t)(t + 1) * 16;
            hA[u] = *(const float4*)(Hn + cb);
            hC[u] = *(const float4*)(Hn + 8 + cb);
            yv[u] = *(const float2*)(yb[u] + (size_t)(t + 1) * 2);
        }

#pragma unroll
        for (int u = 0; u < 2; ++u) {
            // F quarters to SMEM
            *(float4*)(wsp[u] + fblk + frow + fcof) =
                make_float4(fa[u][0], fa[u][1], fa[u][2], fa[u][3]);
            *(float4*)(wsp[u] + fblk + frow + 8 + fcof) =
                make_float4(fr2[u][0], fr2[u][1], fr2[u][2], fr2[u][3]);

            // HP partials (P symmetric)
            float h0a = 0.f, h1a = 0.f, h0b = 0.f, h1b = 0.f;
#pragma unroll
            for (int m = 0; m < 4; ++m) {
                h0a += hao[u][m] * pra[u][m];
                h1a += hco[u][m] * pra[u][m];
                h0b += hao[u][m] * prb[u][m];
                h1b += hco[u][m] * prb[u][m];
            }
            h0a += __shfl_xor_sync(FULL, h0a, 4);
            h1a += __shfl_xor_sync(FULL, h1a, 4);
            h0b += __shfl_xor_sync(FULL, h0b, 4);
            h1b += __shfl_xor_sync(FULL, h1b, 4);
            hp0a[u]=h0a; hp1a[u]=h1a; hp0b[u]=h0b; hp1b[u]=h1b;
            if (c == 0)
                *(float4*)(wsp[u] + ohpw) = make_float4(h0a, h1a, h0b, h1b);

            // residual partials (prev-step mean, synced last iter)
            const float4 mo = *(const float4*)(wsp[u] + OMN + cb);
            float r0p = hao[u][0]*mo.x + hao[u][1]*mo.y + hao[u][2]*mo.z + hao[u][3]*mo.w;
            float r1p = hco[u][0]*mo.x + hco[u][1]*mo.y + hco[u][2]*mo.z + hco[u][3]*mo.w;
            r0[u] = y0[u] - (r0p + __shfl_xor_sync(FULL, r0p, 4));
            r1[u] = y1[u] - (r1p + __shfl_xor_sync(FULL, r1p, 4));

            // other-half quarters of own F rows from c-partner
#pragma unroll
            for (int m = 0; m < 4; ++m) {
                foa[u][m] = __shfl_xor_sync(FULL, fa[u][m], 4);
                fob[u][m] = __shfl_xor_sync(FULL, fr2[u][m], 4);
            }
        }
        __syncwarp();  // sync A: sF, sHP visible

        // ---- phase 2: Smat, gains, P_u, mean_u ----
#pragma unroll
        for (int u = 0; u < 2; ++u) {
            float HP0o[4], HP1o[4];
            {
                const float4 u0 = *(const float4*)(wsp[u] + ohp);
                const float4 u1 = *(const float4*)(wsp[u] + ohp + 4);
                HP0o[0]=u0.x; HP1o[0]=u0.y; HP0o[1]=u0.z; HP1o[1]=u0.w;
                HP0o[2]=u1.x; HP1o[2]=u1.y; HP0o[3]=u1.z; HP1o[3]=u1.w;
            }
            float s00p = 0.f, s01p = 0.f, s10p = 0.f, s11p = 0.f;
#pragma unroll
            for (int m = 0; m < 4; ++m) {
                s00p += HP0o[m] * hao[u][m];
                s01p += HP0o[m] * hco[u][m];
                s10p += HP1o[m] * hao[u][m];
                s11p += HP1o[m] * hco[u][m];
            }
            const float s00 = R00 + s00p + __shfl_xor_sync(FULL, s00p, 4);
            const float s01 = R01 + s01p + __shfl_xor_sync(FULL, s01p, 4);
            const float s10 = R10 + s10p + __shfl_xor_sync(FULL, s10p, 4);
            const float s11 = R11 + s11p + __shfl_xor_sync(FULL, s11p, 4);
            const float inv = 1.0f / (s00 * s11 - s01 * s10);
            const float w0a = inv * ( s11 * hp0a[u] - s01 * hp1a[u]);
            const float w1a = inv * (-s10 * hp0a[u] + s00 * hp1a[u]);
            const float w0b = inv * ( s11 * hp0b[u] - s01 * hp1b[u]);
            const float w1b = inv * (-s10 * hp0b[u] + s00 * hp1b[u]);

            float pua[4], pub[4];
#pragma unroll
            for (int m = 0; m < 4; ++m) {
                pua[m] = pra[u][m] - w0a * HP0o[m] - w1a * HP1o[m];
                pub[m] = prb[u][m] - w0b * HP0o[m] - w1b * HP1o[m];
            }
            *(float4*)(wsp[u] + opu + ra * 4) =
                make_float4(pua[0], pua[1], pua[2], pua[3]);
            *(float4*)(wsp[u] + opu + (ra + 1) * 4) =
                make_float4(pub[0], pub[1], pub[2], pub[3]);

            if (c == 0) {
                const float2 mpair = *(const float2*)(wsp[u] + OMN + ra);
                *(float2*)(wsp[u] + OMU + ra) =
                    make_float2(mpair.x + w0a * r0[u] + w1a * r1[u],
                                mpair.y + w0b * r0[u] + w1b * r1[u]);
            }
        }
        __syncwarp();  // sync B: sPU, sMU visible; sMean reads done

        // ---- phase 3: predict ----
#pragma unroll
        for (int u = 0; u < 2; ++u) {
            float g0=0.f,g1=0.f,g2=0.f,g3=0.f, e0=0.f,e1=0.f,e2=0.f,e3=0.f;
#pragma unroll
            for (int m = 0; m < 4; ++m) {
                const float4 pj = *(const float4*)(wsp[u] + opu + (cb + m) * 4);
                g0 += fa[u][m]  * pj.x; g1 += fa[u][m]  * pj.y;
                g2 += fa[u][m]  * pj.z; g3 += fa[u][m]  * pj.w;
                e0 += fr2[u][m] * pj.x; e1 += fr2[u][m] * pj.y;
                e2 += fr2[u][m] * pj.z; e3 += fr2[u][m] * pj.w;
            }
#pragma unroll
            for (int m = 0; m < 4; ++m) {
                const float4 pj = *(const float4*)(wsp[u] + opu + (ob + m) * 4);
                g0 += foa[u][m] * pj.x; g1 += foa[u][m] * pj.y;
                g2 += foa[u][m] * pj.z; g3 += foa[u][m] * pj.w;
                e0 += fob[u][m] * pj.x; e1 += fob[u][m] * pj.y;
                e2 += fob[u][m] * pj.z; e3 += fob[u][m] * pj.w;
            }
            const float x0 = __shfl_xor_sync(FULL, g0, 4);
            const float x1 = __shfl_xor_sync(FULL, g1, 4);
            const float x2 = __shfl_xor_sync(FULL, g2, 4);
            const float x3 = __shfl_xor_sync(FULL, g3, 4);
            const float z0 = __shfl_xor_sync(FULL, e0, 4);
            const float z1 = __shfl_xor_sync(FULL, e1, 4);
            const float z2 = __shfl_xor_sync(FULL, e2, 4);
            const float z3 = __shfl_xor_sync(FULL, e3, 4);

            float pna[4], pnb[4];
#pragma unroll
            for (int kk = 0; kk < 4; ++kk) {
                const float4 qo = *(const float4*)(wsp[u] + ofk + kk * 8);
                const float4 qt = *(const float4*)(wsp[u] + ofk + kk * 8 + 4);
                pna[kk] = Qa[kk]
                        + g0*qo.x + g1*qo.y + g2*qo.z + g3*qo.w
                        + x0*qt.x + x1*qt.y + x2*qt.z + x3*qt.w;
                pnb[kk] = Qb[kk]
                        + e0*qo.x + e1*qo.y + e2*qo.z + e3*qo.w
                        + z0*qt.x + z1*qt.y + z2*qt.z + z3*qt.w;
            }
#pragma unroll
            for (int m = 0; m < 4; ++m) { pra[u][m] = pna[m]; prb[u][m] = pnb[m]; }

            *(float4*)(ocb[u] + (size_t)(t + 1) * 64 + ra * 8 + cb) =
                make_float4(pna[0], pna[1], pna[2], pna[3]);
            *(float4*)(ocb[u] + (size_t)(t + 1) * 64 + (ra + 1) * 8 + cb) =
                make_float4(pnb[0], pnb[1], pnb[2], pnb[3]);

            if (c == 0) {
                const float4 u0 = *(const float4*)(wsp[u] + OMU);
                const float4 u1 = *(const float4*)(wsp[u] + OMU + 4);
                const float mpa =
                      fa[u][0]*u0.x + fa[u][1]*u0.y + fa[u][2]*u0.z + fa[u][3]*u0.w
                    + foa[u][0]*u1.x + foa[u][1]*u1.y + foa[u][2]*u1.z + foa[u][3]*u1.w;
                const float mpb =
                      fr2[u][0]*u0.x + fr2[u][1]*u0.y + fr2[u][2]*u0.z + fr2[u][3]*u0.w
                    + fob[u][0]*u1.x + fob[u][1]*u1.y + fob[u][2]*u1.z + fob[u][3]*u1.w;
                *(float2*)(wsp[u] + OMN + ra) = make_float2(mpa, mpb);
                *(float2*)(omb[u] + (size_t)(t + 1) * 8 + ra) = make_float2(mpa, mpb);
            }
        }
        __syncwarp();  // sync C: phase-3 reads done; sMean visible next iter
    }
}

extern "C" void kernel_launch(void* const* d_in, const int* in_sizes, int n_in,
                              void* d_out, int out_size)
{
    // metadata order: y, F, H, Q, R, init_mean, init_cov, n_step
    const float* gy     = (const float*)d_in[0];
    const float* gF     = (const float*)d_in[1];
    const float* gH     = (const float*)d_in[2];
    const float* gQ     = (const float*)d_in[3];
    const float* gR     = (const float*)d_in[4];
    const float* gMean0 = (const float*)d_in[5];
    const float* gCov0  = (const float*)d_in[6];
    (void)in_sizes; (void)n_in;

    float* oMean = (float*)d_out;                          // [B,T,8]
    float* oCov  = (float*)d_out + (size_t)Bb * Tt * 8;    // [B,T,8,8]
    (void)out_size;

    kalman_kernel<<<Bb / 8, 32>>>(gy, gF, gH, gQ, gR, gMean0, gCov0,
                                  oMean, oCov);
}